// round 14
// baseline (speedup 1.0000x reference)
#include <cuda_runtime.h>
#include <cuda_fp16.h>
#include <math.h>
#include <stdint.h>

#define T_LEN   2048
#define PAD     2689
#define XS_LEN  7520          // covers prefetch to frag 340 (byte 15040) + slack
#define NFRAGS  620
// scale order (desc): slot 0..4 = widths 336,167,76,27,1 ; out s = 4-slot

__constant__ int c_wdesc[5] = {336, 167, 76, 27, 1};
__constant__ int c_ja[5]    = {0, 83, 129, 153, 166};
__constant__ int c_jb[5]    = {336, 252, 207, 182, 169};

// B fragments, pre-swizzled to mma.m16n8k16 B-register order, packed by Pj.
__device__ __align__(16) __half g_B[NFRAGS * 128];

__device__ __forceinline__ int clampi(int v, int lo, int hi) {
    return v < lo ? lo : (v > hi ? hi : v);
}
__device__ __forceinline__ int Pj(int j) {
    return j + clampi(j - 83, 0, 170) + clampi(j - 129, 0, 79)
             + clampi(j - 153, 0, 30) + clampi(j - 166, 0, 4);
}
// compile-time twins for the static chain (fold after full unroll)
__host__ __device__ constexpr int cclamp(int v, int lo, int hi) {
    return v < lo ? lo : (v > hi ? hi : v);
}
__host__ __device__ constexpr int ns_of(int j) {
    return (j < 83) ? 1 : (j < 129) ? 2 : (j < 153) ? 3 : (j < 166) ? 4 :
           (j < 170) ? 5 : (j < 183) ? 4 : (j < 208) ? 3 : (j < 253) ? 2 : 1;
}
__host__ __device__ constexpr int pj_of(int j) {
    return j + cclamp(j - 83, 0, 170) + cclamp(j - 129, 0, 79)
             + cclamp(j - 153, 0, 30) + cclamp(j - 166, 0, 4);
}

__device__ __forceinline__ uint32_t smem_u32(const void* p) {
    uint32_t a;
    asm("{ .reg .u64 t; cvta.to.shared.u64 t, %1; cvt.u32.u64 %0, t; }" : "=r"(a) : "l"(p));
    return a;
}
__device__ __forceinline__ uint32_t pack2(__half a, __half b) {
    __half2 h = __halves2half2(a, b);
    uint32_t u;
    memcpy(&u, &h, 4);
    return u;
}
#define LDMX4(r, addr) \
    asm volatile("ldmatrix.sync.aligned.m8n8.x4.shared.b16 {%0,%1,%2,%3}, [%4];" \
        : "=r"((r)[0]), "=r"((r)[1]), "=r"((r)[2]), "=r"((r)[3]) : "r"(addr))
#define MMA16816(d, a, b0, b1) \
    asm volatile("mma.sync.aligned.m16n8k16.row.col.f32.f16.f16.f32 " \
        "{%0,%1,%2,%3}, {%4,%5,%6,%7}, {%8,%9}, {%0,%1,%2,%3};" \
        : "+f"((d)[0]), "+f"((d)[1]), "+f"((d)[2]), "+f"((d)[3]) \
        : "r"((a)[0]), "r"((a)[1]), "r"((a)[2]), "r"((a)[3]), "r"(b0), "r"(b1))

// ---------------------------------------------------------------------------
// Setup: identical to R9/R12 (proven): 5 blocks, psi -> fp64 Kogge-Stone scan
// -> f[m] table (one fp64 div per m) -> pre-swizzled packed B fragments.
// ---------------------------------------------------------------------------
__global__ void k_setup() {
    __shared__ double ips[1024];
    __shared__ float  sh_f[5377];
    __shared__ int sh_Lf;
    int tid = threadIdx.x;
    int sidx = blockIdx.x;
    int scale = c_wdesc[sidx];

    double delta = 16.0 / 1023.0;
    double step  = __dsub_rn(__dadd_rn(__dmul_rn(1.0, delta), -8.0), -8.0);

    double t = (tid == 1023) ? 8.0 : __dadd_rn(__dmul_rn((double)tid, delta), -8.0);
    ips[tid] = __dmul_rn(exp(__dmul_rn(-0.5, __dmul_rn(t, t))), cos(__dmul_rn(5.0, t)));
    __syncthreads();
    for (int off = 1; off < 1024; off <<= 1) {
        double a = (tid >= off) ? ips[tid - off] : 0.0;
        __syncthreads();
        ips[tid] = __dadd_rn(ips[tid], a);
        __syncthreads();
    }

    double sstep = __dmul_rn((double)scale, step);
    int Lmax = scale * 16;
    if (tid == 0) {
        long long jm = (long long)(__ddiv_rn((double)Lmax, sstep));
        int Lf;
        if (jm < 1024) {
            Lf = Lmax + 1;
        } else {
            int lo = 0, hi = Lmax;
            while (lo < hi) {
                int mid = (lo + hi) >> 1;
                long long j = (long long)(__ddiv_rn((double)mid, sstep));
                if (j >= 1024) hi = mid; else lo = mid + 1;
            }
            Lf = lo;
        }
        sh_Lf = Lf;
    }
    __syncthreads();
    int Lf = sh_Lf;
    int center = Lf - 1 - (Lf - 2) / 2;
    int Ds = PAD - center;
    float negs = -(float)sqrt((double)scale);

    for (int m = tid; m < Lf; m += 1024) {
        long long ji = (long long)__ddiv_rn((double)m, sstep);
        sh_f[m] = (float)__dmul_rn(ips[ji], step);
    }
    __syncthreads();

    int ja = c_ja[sidx], jb = c_jb[sidx];
    int nj = jb - ja + 1;
    for (int it = tid; it < nj * 32; it += 1024) {
        int j = ja + (it >> 5);
        int lane = it & 31;
        int k0 = 16 * j + 2 * (lane & 3);
        int nn = lane >> 2;
        __half wh[4];
        #pragma unroll
        for (int q = 0; q < 4; ++q) {
            int k = k0 + (q & 1) + (q >> 1) * 8;
            int m = k - nn - Ds;
            float v = 0.f;
            if (m >= 0 && m <= Lf) {
                float fm1 = (m >= 1) ? sh_f[m - 1] : 0.f;
                float fc  = (m <  Lf) ? sh_f[m]     : 0.f;
                v = (fm1 - fc) * negs;
            }
            wh[q] = __float2half(v);
        }
        size_t fb = (size_t)(Pj(j) + sidx) * 256;
        uint2* dsth = (uint2*)((char*)g_B + fb + lane * 8);
        *dsth = make_uint2(pack2(wh[0], wh[1]), pack2(wh[2], wh[3]));
    }
}

// ---------------------------------------------------------------------------
// Static chain, batched 8 kstep bodies per template level (depth 43).
// Single m16-tile per warp. 4-slot A ring, prefetch distance 4: on entry to
// body j, slot (j+i)%4 holds frag(j+i), i=0..3. Use frag(j), then prefetch
// frag(j+4) into the retiring slot. All indices/offsets compile-time.
// ---------------------------------------------------------------------------
#define NBODY 337
template<int J>
struct Chain {
    static __device__ __forceinline__ void go(uint32_t (&ring)[4][4],
                                              float (&D)[5][4],
                                              uint32_t abase,
                                              const char* __restrict__ gb) {
        constexpr int CNT = (NBODY - J < 8) ? (NBODY - J) : 8;
        #pragma unroll
        for (int jj = 0; jj < CNT; ++jj) {
            const int j  = J + jj;
            const int NS = ns_of(j);
            const int BO = 256 * pj_of(j);
            const int P  = j & 3;
            uint2 b[5];
            #pragma unroll
            for (int si = 0; si < 5; ++si)
                if (si < NS) b[si] = *(const uint2*)(gb + BO + si * 256);
            #pragma unroll
            for (int si = 0; si < 5; ++si)
                if (si < NS) MMA16816(D[si], ring[P], b[si].x, b[si].y);
            LDMX4(ring[P], abase + (j + 4) * 32);  // prefetch frag(j+4)
        }
        Chain<J + 8>::go(ring, D, abase, gb);
    }
};
template<>
struct Chain<344> {
    static __device__ __forceinline__ void go(uint32_t (&)[4][4], float (&)[5][4],
                                              uint32_t, const char*) {}
};

// ---------------------------------------------------------------------------
// Main kernel: one CTA = one (batch, channel) row. 512 threads = 16 warps =
// 16 m16-tiles of 128 outputs each. Low reg footprint (~58) so 2 CTAs/SM =
// 32 warps/SM: 2x warp-level parallelism vs R13, shorter per-warp chains.
// ---------------------------------------------------------------------------
__global__ void __launch_bounds__(512, 2) k_tc(const float* __restrict__ x,
                                               float* __restrict__ out) {
    __shared__ __align__(16) __half xs[XS_LEN];
    int tid = threadIdx.x;
    int wid = tid >> 5, lane = tid & 31;
    int row = blockIdx.x;
    int nb = row >> 6, c = row & 63;

    // prologue: padded row -> fp16
    const float* xrow = x + (size_t)nb * T_LEN * 64 + c;
    for (int i = tid; i < XS_LEN; i += 512) {
        int g = i - PAD;
        xs[i] = (g >= 0 && g < T_LEN) ? __float2half(__ldg(xrow + (size_t)g * 64)) : __half(0.f);
    }
    __syncthreads();

    int t0 = wid * 128;   // 16 warps x 1 m16-tile (128 outputs)
    uint32_t abase = smem_u32(xs) + 2u * (uint32_t)(t0 + 8 * (lane & 15) + 8 * (lane >> 4));
    const char* gb = (const char*)g_B + lane * 8;

    float D[5][4];
    #pragma unroll
    for (int si = 0; si < 5; ++si)
        #pragma unroll
        for (int q = 0; q < 4; ++q) D[si][q] = 0.f;

    uint32_t ring[4][4];
    #pragma unroll
    for (int f = 0; f < 4; ++f)
        LDMX4(ring[f], abase + f * 32);

    Chain<0>::go(ring, D, abase, gb);

    // epilogue: D[m][n] -> out[t0 + 8m + n], slot si -> s = 4-si
    int mrow = lane >> 2;
    int ncol = (lane & 3) * 2;
    #pragma unroll
    for (int si = 0; si < 5; ++si) {
        int s_out = 4 - si;
        int t00 = t0 + 8 * mrow + ncol;
        float* o = out + ((size_t)(nb * T_LEN + t00) * 64 + c) * 5 + s_out;
        o[0]        = D[si][0];
        o[320]      = D[si][1];   // t+1
        o[64 * 320] = D[si][2];   // t+64 (m+8)
        o[65 * 320] = D[si][3];
    }
}

extern "C" void kernel_launch(void* const* d_in, const int* in_sizes, int n_in,
                              void* d_out, int out_size) {
    const float* x = (const float*)d_in[0];
    float* out = (float*)d_out;
    (void)in_sizes; (void)n_in; (void)out_size;

    k_setup<<<5, 1024>>>();
    k_tc<<<1024, 512>>>(x, out);
}

// round 15
// speedup vs baseline: 1.2350x; 1.2350x over previous
#include <cuda_runtime.h>
#include <cuda_fp16.h>
#include <math.h>
#include <stdint.h>

#define T_LEN   2048
#define PAD     2689
#define CHUNK   1024
#define XS_LEN  6464          // covers A cols up to prefetch frag 346 (max 6439)
#define NFRAGS  620
// scale order (desc): slot 0..4 = widths 336,167,76,27,1 ; out s = 4-slot

__constant__ int c_wdesc[5] = {336, 167, 76, 27, 1};
__constant__ int c_ja[5]    = {0, 83, 129, 153, 166};
__constant__ int c_jb[5]    = {336, 252, 207, 182, 169};

// B fragments, pre-swizzled to mma.m16n8k16 B-register order, packed by Pj.
__device__ __align__(16) __half g_B[NFRAGS * 128];

__device__ __forceinline__ int clampi(int v, int lo, int hi) {
    return v < lo ? lo : (v > hi ? hi : v);
}
__device__ __forceinline__ int Pj(int j) {
    return j + clampi(j - 83, 0, 170) + clampi(j - 129, 0, 79)
             + clampi(j - 153, 0, 30) + clampi(j - 166, 0, 4);
}
// compile-time twins for the static chain (fold after full unroll)
__host__ __device__ constexpr int cclamp(int v, int lo, int hi) {
    return v < lo ? lo : (v > hi ? hi : v);
}
__host__ __device__ constexpr int ns_of(int j) {
    return (j < 83) ? 1 : (j < 129) ? 2 : (j < 153) ? 3 : (j < 166) ? 4 :
           (j < 170) ? 5 : (j < 183) ? 4 : (j < 208) ? 3 : (j < 253) ? 2 : 1;
}
__host__ __device__ constexpr int pj_of(int j) {
    return j + cclamp(j - 83, 0, 170) + cclamp(j - 129, 0, 79)
             + cclamp(j - 153, 0, 30) + cclamp(j - 166, 0, 4);
}

__device__ __forceinline__ uint32_t smem_u32(const void* p) {
    uint32_t a;
    asm("{ .reg .u64 t; cvta.to.shared.u64 t, %1; cvt.u32.u64 %0, t; }" : "=r"(a) : "l"(p));
    return a;
}
__device__ __forceinline__ uint32_t pack2(__half a, __half b) {
    __half2 h = __halves2half2(a, b);
    uint32_t u;
    memcpy(&u, &h, 4);
    return u;
}
#define LDMX4(r, addr) \
    asm volatile("ldmatrix.sync.aligned.m8n8.x4.shared.b16 {%0,%1,%2,%3}, [%4];" \
        : "=r"((r)[0]), "=r"((r)[1]), "=r"((r)[2]), "=r"((r)[3]) : "r"(addr))
#define MMA16816(d, a, b0, b1) \
    asm volatile("mma.sync.aligned.m16n8k16.row.col.f32.f16.f16.f32 " \
        "{%0,%1,%2,%3}, {%4,%5,%6,%7}, {%8,%9}, {%0,%1,%2,%3};" \
        : "+f"((d)[0]), "+f"((d)[1]), "+f"((d)[2]), "+f"((d)[3]) \
        : "r"((a)[0]), "r"((a)[1]), "r"((a)[2]), "r"((a)[3]), "r"(b0), "r"(b1))

// ---------------------------------------------------------------------------
// Setup: identical to R9/R12 (proven): 5 blocks, psi -> fp64 Kogge-Stone scan
// -> f[m] table (one fp64 div per m) -> pre-swizzled packed B fragments.
// ---------------------------------------------------------------------------
__global__ void k_setup() {
    __shared__ double ips[1024];
    __shared__ float  sh_f[5377];
    __shared__ int sh_Lf;
    int tid = threadIdx.x;
    int sidx = blockIdx.x;
    int scale = c_wdesc[sidx];

    double delta = 16.0 / 1023.0;
    double step  = __dsub_rn(__dadd_rn(__dmul_rn(1.0, delta), -8.0), -8.0);

    double t = (tid == 1023) ? 8.0 : __dadd_rn(__dmul_rn((double)tid, delta), -8.0);
    ips[tid] = __dmul_rn(exp(__dmul_rn(-0.5, __dmul_rn(t, t))), cos(__dmul_rn(5.0, t)));
    __syncthreads();
    for (int off = 1; off < 1024; off <<= 1) {
        double a = (tid >= off) ? ips[tid - off] : 0.0;
        __syncthreads();
        ips[tid] = __dadd_rn(ips[tid], a);
        __syncthreads();
    }

    double sstep = __dmul_rn((double)scale, step);
    int Lmax = scale * 16;
    if (tid == 0) {
        long long jm = (long long)(__ddiv_rn((double)Lmax, sstep));
        int Lf;
        if (jm < 1024) {
            Lf = Lmax + 1;
        } else {
            int lo = 0, hi = Lmax;
            while (lo < hi) {
                int mid = (lo + hi) >> 1;
                long long j = (long long)(__ddiv_rn((double)mid, sstep));
                if (j >= 1024) hi = mid; else lo = mid + 1;
            }
            Lf = lo;
        }
        sh_Lf = Lf;
    }
    __syncthreads();
    int Lf = sh_Lf;
    int center = Lf - 1 - (Lf - 2) / 2;
    int Ds = PAD - center;
    float negs = -(float)sqrt((double)scale);

    for (int m = tid; m < Lf; m += 1024) {
        long long ji = (long long)__ddiv_rn((double)m, sstep);
        sh_f[m] = (float)__dmul_rn(ips[ji], step);
    }
    __syncthreads();

    int ja = c_ja[sidx], jb = c_jb[sidx];
    int nj = jb - ja + 1;
    for (int it = tid; it < nj * 32; it += 1024) {
        int j = ja + (it >> 5);
        int lane = it & 31;
        int k0 = 16 * j + 2 * (lane & 3);
        int nn = lane >> 2;
        __half wh[4];
        #pragma unroll
        for (int q = 0; q < 4; ++q) {
            int k = k0 + (q & 1) + (q >> 1) * 8;
            int m = k - nn - Ds;
            float v = 0.f;
            if (m >= 0 && m <= Lf) {
                float fm1 = (m >= 1) ? sh_f[m - 1] : 0.f;
                float fc  = (m <  Lf) ? sh_f[m]     : 0.f;
                v = (fm1 - fc) * negs;
            }
            wh[q] = __float2half(v);
        }
        size_t fb = (size_t)(Pj(j) + sidx) * 256;
        uint2* dsth = (uint2*)((char*)g_B + fb + lane * 8);
        *dsth = make_uint2(pack2(wh[0], wh[1]), pack2(wh[2], wh[3]));
    }
}

// ---------------------------------------------------------------------------
// Static chain, batched 8 kstep bodies per template level (depth 43).
// A ring: on entry to body j, ring[(j+i)%10] holds frag(j+i), i=0..9; mt0
// uses frag(j), mt1 frag(j+8); prefetch frag(j+10) into the retiring slot.
// B double-buffer: on entry, b[j&1] holds B(j); body j first issues B(j+1)
// loads into b[(j+1)&1] (a full body of MMA latency cover), then runs MMAs.
// After full unroll all indices/offsets are compile-time constants.
// ---------------------------------------------------------------------------
#define NBODY 337
template<int J>
struct Chain {
    static __device__ __forceinline__ void go(uint32_t (&ring)[10][4],
                                              float (&D)[5][2][4],
                                              uint2 (&b)[2][5],
                                              uint32_t abase,
                                              const char* __restrict__ gb) {
        constexpr int CNT = (NBODY - J < 8) ? (NBODY - J) : 8;
        #pragma unroll
        for (int jj = 0; jj < CNT; ++jj) {
            const int j   = J + jj;
            const int cur = j & 1;
            const int nxt = cur ^ 1;
            // prefetch B(j+1)
            if (j + 1 < NBODY) {
                const int NSn = ns_of(j + 1);
                const int BOn = 256 * pj_of(j + 1);
                #pragma unroll
                for (int si = 0; si < 5; ++si)
                    if (si < NSn) b[nxt][si] = *(const uint2*)(gb + BOn + si * 256);
            }
            const int NS = ns_of(j);
            const int P0 = j % 10;
            const int P1 = (j + 8) % 10;
            #pragma unroll
            for (int si = 0; si < 5; ++si)
                if (si < NS) MMA16816(D[si][0], ring[P0], b[cur][si].x, b[cur][si].y);
            LDMX4(ring[P0], abase + (j + 10) * 32);  // prefetch frag(j+10)
            #pragma unroll
            for (int si = 0; si < 5; ++si)
                if (si < NS) MMA16816(D[si][1], ring[P1], b[cur][si].x, b[cur][si].y);
        }
        Chain<J + 8>::go(ring, D, b, abase, gb);
    }
};
template<>
struct Chain<344> {
    static __device__ __forceinline__ void go(uint32_t (&)[10][4], float (&)[5][2][4],
                                              uint2 (&)[2][5], uint32_t, const char*) {}
};

// ---------------------------------------------------------------------------
// Main kernel (R12 shape): half-row CTAs (grid 2048 = row*2chunks), 128
// threads, 4 warps x 2 m16-tiles (256 outputs each), 4 CTAs/SM. A frags via
// Toeplitz ldmatrix, each loaded once (ring); B double-buffered in registers.
// ---------------------------------------------------------------------------
__global__ void __launch_bounds__(128, 4) k_tc(const float* __restrict__ x,
                                               float* __restrict__ out) {
    __shared__ __align__(16) __half xs[XS_LEN];
    int tid = threadIdx.x;
    int wid = tid >> 5, lane = tid & 31;
    int bid = blockIdx.x;
    int row = bid >> 1;
    int cb  = (bid & 1) * CHUNK;
    int nb = row >> 6, c = row & 63;

    // prologue: padded chunk -> fp16 (xs[i] = x[cb + i - PAD])
    const float* xrow = x + (size_t)nb * T_LEN * 64 + c;
    for (int i = tid; i < XS_LEN; i += 128) {
        int g = cb + i - PAD;
        xs[i] = (g >= 0 && g < T_LEN) ? __float2half(__ldg(xrow + (size_t)g * 64)) : __half(0.f);
    }
    __syncthreads();

    int t0 = wid * 256;   // 4 warps x 256 outputs (2 m16-tiles each)
    uint32_t abase = smem_u32(xs) + 2u * (uint32_t)(t0 + 8 * (lane & 15) + 8 * (lane >> 4));
    const char* gb = (const char*)g_B + lane * 8;

    float D[5][2][4];
    #pragma unroll
    for (int si = 0; si < 5; ++si)
        #pragma unroll
        for (int mt = 0; mt < 2; ++mt)
            #pragma unroll
            for (int q = 0; q < 4; ++q) D[si][mt][q] = 0.f;

    uint32_t ring[10][4];
    #pragma unroll
    for (int f = 0; f < 10; ++f)
        LDMX4(ring[f], abase + f * 32);

    uint2 b[2][5];
    b[0][0] = *(const uint2*)(gb + 256 * pj_of(0));   // B(0), NS(0)=1

    Chain<0>::go(ring, D, b, abase, gb);

    // epilogue: D[m][n] -> out[cb + t0 + 128*mt + 8m + n], slot si -> s = 4-si
    int mrow = lane >> 2;
    int ncol = (lane & 3) * 2;
    #pragma unroll
    for (int si = 0; si < 5; ++si) {
        int s_out = 4 - si;
        #pragma unroll
        for (int mt = 0; mt < 2; ++mt) {
            int t00 = cb + t0 + mt * 128 + 8 * mrow + ncol;
            float* o = out + ((size_t)(nb * T_LEN + t00) * 64 + c) * 5 + s_out;
            o[0]        = D[si][mt][0];
            o[320]      = D[si][mt][1];   // t+1
            o[64 * 320] = D[si][mt][2];   // t+64 (m+8)
            o[65 * 320] = D[si][mt][3];
        }
    }
}

extern "C" void kernel_launch(void* const* d_in, const int* in_sizes, int n_in,
                              void* d_out, int out_size) {
    const float* x = (const float*)d_in[0];
    float* out = (float*)d_out;
    (void)in_sizes; (void)n_in; (void)out_size;

    k_setup<<<5, 1024>>>();
    k_tc<<<2048, 128>>>(x, out);
}

// round 16
// speedup vs baseline: 1.2674x; 1.0262x over previous
#include <cuda_runtime.h>
#include <cuda_fp16.h>
#include <math.h>
#include <stdint.h>

#define T_LEN   2048
#define PAD     2689
#define CHUNK   1024
#define XS_LEN  6464          // covers A cols up to prefetch frag 346 (max 6439)
#define NFRAGS  620
// scale order (desc): slot 0..4 = widths 336,167,76,27,1 ; out s = 4-slot

__constant__ int c_wdesc[5] = {336, 167, 76, 27, 1};
__constant__ int c_ja[5]    = {0, 83, 129, 153, 166};
__constant__ int c_jb[5]    = {336, 252, 207, 182, 169};

// B fragments, pre-swizzled to mma.m16n8k16 B-register order, packed by Pj.
__device__ __align__(16) __half g_B[NFRAGS * 128];

__device__ __forceinline__ int clampi(int v, int lo, int hi) {
    return v < lo ? lo : (v > hi ? hi : v);
}
__device__ __forceinline__ int Pj(int j) {
    return j + clampi(j - 83, 0, 170) + clampi(j - 129, 0, 79)
             + clampi(j - 153, 0, 30) + clampi(j - 166, 0, 4);
}
// compile-time twins for the static chain (fold after full unroll)
__host__ __device__ constexpr int cclamp(int v, int lo, int hi) {
    return v < lo ? lo : (v > hi ? hi : v);
}
__host__ __device__ constexpr int ns_of(int j) {
    return (j < 83) ? 1 : (j < 129) ? 2 : (j < 153) ? 3 : (j < 166) ? 4 :
           (j < 170) ? 5 : (j < 183) ? 4 : (j < 208) ? 3 : (j < 253) ? 2 : 1;
}
__host__ __device__ constexpr int pj_of(int j) {
    return j + cclamp(j - 83, 0, 170) + cclamp(j - 129, 0, 79)
             + cclamp(j - 153, 0, 30) + cclamp(j - 166, 0, 4);
}

__device__ __forceinline__ uint32_t smem_u32(const void* p) {
    uint32_t a;
    asm("{ .reg .u64 t; cvta.to.shared.u64 t, %1; cvt.u32.u64 %0, t; }" : "=r"(a) : "l"(p));
    return a;
}
__device__ __forceinline__ uint32_t pack2(__half a, __half b) {
    __half2 h = __halves2half2(a, b);
    uint32_t u;
    memcpy(&u, &h, 4);
    return u;
}
#define LDMX4(r, addr) \
    asm volatile("ldmatrix.sync.aligned.m8n8.x4.shared.b16 {%0,%1,%2,%3}, [%4];" \
        : "=r"((r)[0]), "=r"((r)[1]), "=r"((r)[2]), "=r"((r)[3]) : "r"(addr))
#define MMA16816(d, a, b0, b1) \
    asm volatile("mma.sync.aligned.m16n8k16.row.col.f32.f16.f16.f32 " \
        "{%0,%1,%2,%3}, {%4,%5,%6,%7}, {%8,%9}, {%0,%1,%2,%3};" \
        : "+f"((d)[0]), "+f"((d)[1]), "+f"((d)[2]), "+f"((d)[3]) \
        : "r"((a)[0]), "r"((a)[1]), "r"((a)[2]), "r"((a)[3]), "r"(b0), "r"(b1))

// ---------------------------------------------------------------------------
// Setup: identical to R9/R12 (proven): 5 blocks, psi -> fp64 Kogge-Stone scan
// -> f[m] table (one fp64 div per m) -> pre-swizzled packed B fragments.
// ---------------------------------------------------------------------------
__global__ void k_setup() {
    __shared__ double ips[1024];
    __shared__ float  sh_f[5377];
    __shared__ int sh_Lf;
    int tid = threadIdx.x;
    int sidx = blockIdx.x;
    int scale = c_wdesc[sidx];

    double delta = 16.0 / 1023.0;
    double step  = __dsub_rn(__dadd_rn(__dmul_rn(1.0, delta), -8.0), -8.0);

    double t = (tid == 1023) ? 8.0 : __dadd_rn(__dmul_rn((double)tid, delta), -8.0);
    ips[tid] = __dmul_rn(exp(__dmul_rn(-0.5, __dmul_rn(t, t))), cos(__dmul_rn(5.0, t)));
    __syncthreads();
    for (int off = 1; off < 1024; off <<= 1) {
        double a = (tid >= off) ? ips[tid - off] : 0.0;
        __syncthreads();
        ips[tid] = __dadd_rn(ips[tid], a);
        __syncthreads();
    }

    double sstep = __dmul_rn((double)scale, step);
    int Lmax = scale * 16;
    if (tid == 0) {
        long long jm = (long long)(__ddiv_rn((double)Lmax, sstep));
        int Lf;
        if (jm < 1024) {
            Lf = Lmax + 1;
        } else {
            int lo = 0, hi = Lmax;
            while (lo < hi) {
                int mid = (lo + hi) >> 1;
                long long j = (long long)(__ddiv_rn((double)mid, sstep));
                if (j >= 1024) hi = mid; else lo = mid + 1;
            }
            Lf = lo;
        }
        sh_Lf = Lf;
    }
    __syncthreads();
    int Lf = sh_Lf;
    int center = Lf - 1 - (Lf - 2) / 2;
    int Ds = PAD - center;
    float negs = -(float)sqrt((double)scale);

    for (int m = tid; m < Lf; m += 1024) {
        long long ji = (long long)__ddiv_rn((double)m, sstep);
        sh_f[m] = (float)__dmul_rn(ips[ji], step);
    }
    __syncthreads();

    int ja = c_ja[sidx], jb = c_jb[sidx];
    int nj = jb - ja + 1;
    for (int it = tid; it < nj * 32; it += 1024) {
        int j = ja + (it >> 5);
        int lane = it & 31;
        int k0 = 16 * j + 2 * (lane & 3);
        int nn = lane >> 2;
        __half wh[4];
        #pragma unroll
        for (int q = 0; q < 4; ++q) {
            int k = k0 + (q & 1) + (q >> 1) * 8;
            int m = k - nn - Ds;
            float v = 0.f;
            if (m >= 0 && m <= Lf) {
                float fm1 = (m >= 1) ? sh_f[m - 1] : 0.f;
                float fc  = (m <  Lf) ? sh_f[m]     : 0.f;
                v = (fm1 - fc) * negs;
            }
            wh[q] = __float2half(v);
        }
        size_t fb = (size_t)(Pj(j) + sidx) * 256;
        uint2* dsth = (uint2*)((char*)g_B + fb + lane * 8);
        *dsth = make_uint2(pack2(wh[0], wh[1]), pack2(wh[2], wh[3]));
    }
}

// ---------------------------------------------------------------------------
// Static chain, batched 8 kstep bodies per template level (depth 43).
// A ring: on entry to body j, ring[(j+i)%10] holds frag(j+i), i=0..9; mt0
// uses frag(j), mt1 frag(j+8); prefetch frag(j+10) into the retiring slot.
// Accumulator RAW fix: slots 0,1 (active in the NS<=2 chain-starved regions)
// keep even/odd-j accumulator copies D2[si][mt][j&1] -> reuse distance 2
// bodies, 4 independent MMA chains per warp in NS=1. Slots 2-4 single copy.
// All indices/offsets/parities are compile-time after the full unroll.
// ---------------------------------------------------------------------------
#define NBODY 337
template<int J>
struct Chain {
    static __device__ __forceinline__ void go(uint32_t (&ring)[10][4],
                                              float (&D2)[2][2][2][4],
                                              float (&D)[3][2][4],
                                              uint32_t abase,
                                              const char* __restrict__ gb) {
        constexpr int CNT = (NBODY - J < 8) ? (NBODY - J) : 8;
        #pragma unroll
        for (int jj = 0; jj < CNT; ++jj) {
            const int j   = J + jj;
            const int NS  = ns_of(j);
            const int BO  = 256 * pj_of(j);
            const int P0  = j % 10;
            const int P1  = (j + 8) % 10;
            const int PAR = j & 1;
            uint2 b[5];
            #pragma unroll
            for (int si = 0; si < 5; ++si)
                if (si < NS) b[si] = *(const uint2*)(gb + BO + si * 256);
            #pragma unroll
            for (int si = 0; si < 5; ++si)
                if (si < NS) {
                    if (si < 2) MMA16816(D2[si][0][PAR], ring[P0], b[si].x, b[si].y);
                    else        MMA16816(D[si - 2][0],   ring[P0], b[si].x, b[si].y);
                }
            LDMX4(ring[P0], abase + (j + 10) * 32);  // prefetch frag(j+10)
            #pragma unroll
            for (int si = 0; si < 5; ++si)
                if (si < NS) {
                    if (si < 2) MMA16816(D2[si][1][PAR], ring[P1], b[si].x, b[si].y);
                    else        MMA16816(D[si - 2][1],   ring[P1], b[si].x, b[si].y);
                }
        }
        Chain<J + 8>::go(ring, D2, D, abase, gb);
    }
};
template<>
struct Chain<344> {
    static __device__ __forceinline__ void go(uint32_t (&)[10][4], float (&)[2][2][2][4],
                                              float (&)[3][2][4], uint32_t, const char*) {}
};

// ---------------------------------------------------------------------------
// Main kernel (R12 shape + split accumulators): half-row CTAs (grid 2048),
// 128 threads, 4 warps x 2 m16-tiles (256 outputs each), 3 CTAs/SM (170-reg
// budget holds the extra accumulator copies without spilling).
// ---------------------------------------------------------------------------
__global__ void __launch_bounds__(128, 3) k_tc(const float* __restrict__ x,
                                               float* __restrict__ out) {
    __shared__ __align__(16) __half xs[XS_LEN];
    int tid = threadIdx.x;
    int wid = tid >> 5, lane = tid & 31;
    int bid = blockIdx.x;
    int row = bid >> 1;
    int cb  = (bid & 1) * CHUNK;
    int nb = row >> 6, c = row & 63;

    // prologue: padded chunk -> fp16 (xs[i] = x[cb + i - PAD])
    const float* xrow = x + (size_t)nb * T_LEN * 64 + c;
    for (int i = tid; i < XS_LEN; i += 128) {
        int g = cb + i - PAD;
        xs[i] = (g >= 0 && g < T_LEN) ? __float2half(__ldg(xrow + (size_t)g * 64)) : __half(0.f);
    }
    __syncthreads();

    int t0 = wid * 256;   // 4 warps x 256 outputs (2 m16-tiles each)
    uint32_t abase = smem_u32(xs) + 2u * (uint32_t)(t0 + 8 * (lane & 15) + 8 * (lane >> 4));
    const char* gb = (const char*)g_B + lane * 8;

    float D2[2][2][2][4];   // slots 0,1: [si][mt][parity][q]
    float D [3][2][4];      // slots 2..4
    #pragma unroll
    for (int si = 0; si < 2; ++si)
        #pragma unroll
        for (int mt = 0; mt < 2; ++mt)
            #pragma unroll
            for (int p = 0; p < 2; ++p)
                #pragma unroll
                for (int q = 0; q < 4; ++q) D2[si][mt][p][q] = 0.f;
    #pragma unroll
    for (int si = 0; si < 3; ++si)
        #pragma unroll
        for (int mt = 0; mt < 2; ++mt)
            #pragma unroll
            for (int q = 0; q < 4; ++q) D[si][mt][q] = 0.f;

    uint32_t ring[10][4];
    #pragma unroll
    for (int f = 0; f < 10; ++f)
        LDMX4(ring[f], abase + f * 32);

    Chain<0>::go(ring, D2, D, abase, gb);

    // epilogue: merge parities; D[m][n] -> out[cb+t0+128*mt+8m+n], s = 4-si
    int mrow = lane >> 2;
    int ncol = (lane & 3) * 2;
    #pragma unroll
    for (int si = 0; si < 5; ++si) {
        int s_out = 4 - si;
        #pragma unroll
        for (int mt = 0; mt < 2; ++mt) {
            float v[4];
            #pragma unroll
            for (int q = 0; q < 4; ++q)
                v[q] = (si < 2) ? (D2[si][mt][0][q] + D2[si][mt][1][q])
                                : D[si - 2][mt][q];
            int t00 = cb + t0 + mt * 128 + 8 * mrow + ncol;
            float* o = out + ((size_t)(nb * T_LEN + t00) * 64 + c) * 5 + s_out;
            o[0]        = v[0];
            o[320]      = v[1];   // t+1
            o[64 * 320] = v[2];   // t+64 (m+8)
            o[65 * 320] = v[3];
        }
    }
}

extern "C" void kernel_launch(void* const* d_in, const int* in_sizes, int n_in,
                              void* d_out, int out_size) {
    const float* x = (const float*)d_in[0];
    float* out = (float*)d_out;
    (void)in_sizes; (void)n_in; (void)out_size;

    k_setup<<<5, 1024>>>();
    k_tc<<<2048, 128>>>(x, out);
}